// round 13
// baseline (speedup 1.0000x reference)
#include <cuda_runtime.h>
#include <cuda_bf16.h>

#define NN 4096
#define DD 128
#define NBLK 148
#define NTHR 1024
#define NWARP 32
#define REGC 0.05f
#define EPSC 1e-8f
#define NITER 12
#define MUNU (1.0f / 4096.0f)
#define L1ROWS 22            // rows kept L1-resident per CTA (176KB of ~210KB L1D)

// Scratch (__device__ globals — sanctioned)
__device__ __nv_bfloat16 g_Kb[(size_t)NN * NN];   // bf16 K row-major (only copy)
__device__ float g_part[(size_t)NBLK * NN];       // per-CTA partial column sums
__device__ float g_v[NN];
__device__ float g_nsq[3 * NN];
__device__ double g_loss;
__device__ unsigned int g_flagsP[256];            // packed 4B-stride flags (all-poll barrier)

__device__ __forceinline__ float bf_lo(unsigned int u) { return __uint_as_float(u << 16); }
__device__ __forceinline__ float bf_hi(unsigned int u) { return __uint_as_float(u & 0xffff0000u); }

__device__ __forceinline__ unsigned int ld_acq(const unsigned int* p) {
    unsigned int v;
    asm volatile("ld.acquire.gpu.global.u32 %0, [%1];" : "=r"(v) : "l"(p) : "memory");
    return v;
}
__device__ __forceinline__ void st_rel(unsigned int* p, unsigned int v) {
    asm volatile("st.release.gpu.global.u32 [%0], %1;" :: "l"(p), "r"(v) : "memory");
}

// Symmetric all-poll grid barrier: every CTA's threads tid<NBLK each spin on
// one packed flag. One L2 round trip after last arrival (no CTA0 relay hop).
// Visibility: peer release-store -> my acquire-load (thread tid) -> __syncthreads
// (CTA-scope fence) -> all threads. Cross-barrier mutable data read .cg;
// K is write-once + explicit IVALL per pair.
__device__ __forceinline__ void grid_barrier(unsigned int& gen, int tid, int bid) {
    __syncthreads();
    ++gen;
    if (tid == 0) st_rel(&g_flagsP[bid], gen);
    if (tid < NBLK) {
        const unsigned int* f = &g_flagsP[tid];
        while ((int)(ld_acq(f) - gen) < 0) { }
    }
    __syncthreads();
}

__device__ __forceinline__ float dot8(uint4 q, float4 va, float4 vb, float acc) {
    acc += bf_lo(q.x) * va.x + bf_hi(q.x) * va.y
         + bf_lo(q.y) * va.z + bf_hi(q.y) * va.w
         + bf_lo(q.z) * vb.x + bf_hi(q.z) * vb.y
         + bf_lo(q.w) * vb.z + bf_hi(q.w) * vb.w;
    return acc;
}

__global__ __launch_bounds__(NTHR, 1) void ot_kernel(
    const float* __restrict__ z0, const float* __restrict__ z1,
    const float* __restrict__ z2, float* __restrict__ out)
{
    // s_mem: GEMM tiles (2 x 16x132 floats = 16.9KB) / v-reduce scratch overlay
    __shared__ __align__(16) float s_mem[2 * 16 * 132];
    __shared__ float s_part[28 * 9];
    __shared__ float s_u[28];
    __shared__ double s_dval[28];

    const int tid  = threadIdx.x;
    const int bid  = blockIdx.x;
    const int wid  = tid >> 5;
    const int lane = tid & 31;
    const int rb    = (int)(((long long)bid * NN) / NBLK);
    const int re    = (int)(((long long)(bid + 1) * NN) / NBLK);
    const int nrows = re - rb;                      // 27 or 28

    unsigned int gen = __ldcg(&g_flagsP[bid]);      // monotonic across graph replays

    if (bid == 0 && tid == 0) g_loss = 0.0;

    const float* Z[3] = { z0, z1, z2 };
    const int XI[3] = { 0, 0, 1 };
    const int YI[3] = { 1, 2, 2 };

    // ---------- Phase 0 (once): row norms of z0,z1,z2 ----------
    for (int r = bid * NWARP + wid; r < 3 * NN; r += NBLK * NWARP) {
        const float* src = Z[r >> 12];
        int row = r & (NN - 1);
        float4 v4 = ((const float4*)(src + (size_t)row * DD))[lane];
        float s = v4.x * v4.x + v4.y * v4.y + v4.z * v4.z + v4.w * v4.w;
        #pragma unroll
        for (int o = 16; o; o >>= 1) s += __shfl_xor_sync(0xffffffffu, s, o);
        if (lane == 0) g_nsq[r] = s;
    }
    grid_barrier(gen, tid, bid);

    for (int pr = 0; pr < 3; ++pr) {
        const float* x = Z[XI[pr]];
        const float* y = Z[YI[pr]];
        const float* xsq = g_nsq + XI[pr] * NN;
        const float* ysq = g_nsq + YI[pr] * NN;

        // ---------- Phase 2: K = exp(-C/REG) -> Kb (row-major only); u := 1 ----------
        {
            float* sxT = s_mem;                  // [16 k][128 i], stride 132
            float* syT = s_mem + 16 * 132;       // [16 k][128 j], stride 132
            const int ty = tid >> 5;             // 0..31 -> 4 rows each
            const int tx = tid & 31;             // 0..31 -> 4 cols each
            const int NT = (NN / 128) * (NN / 128);   // 1024 tiles

            for (int t = bid; t < NT; t += NBLK) {
                const int r0 = (t >> 5) * 128;
                const int c0 = (t & 31) * 128;
                float acc[4][4];
                #pragma unroll
                for (int m = 0; m < 4; ++m)
                    #pragma unroll
                    for (int n = 0; n < 4; ++n) acc[m][n] = 0.f;

                for (int kc = 0; kc < DD; kc += 16) {
                    __syncthreads();
                    #pragma unroll
                    for (int idx = tid; idx < 128 * 16; idx += NTHR) {
                        int rr = idx >> 4, cc = idx & 15;
                        sxT[cc * 132 + rr] = x[(size_t)(r0 + rr) * DD + kc + cc];
                        syT[cc * 132 + rr] = y[(size_t)(c0 + rr) * DD + kc + cc];
                    }
                    __syncthreads();
                    #pragma unroll
                    for (int k = 0; k < 16; ++k) {
                        float4 a4 = *(const float4*)&sxT[k * 132 + ty * 4];
                        float4 b4 = *(const float4*)&syT[k * 132 + tx * 4];
                        acc[0][0] += a4.x * b4.x; acc[0][1] += a4.x * b4.y;
                        acc[0][2] += a4.x * b4.z; acc[0][3] += a4.x * b4.w;
                        acc[1][0] += a4.y * b4.x; acc[1][1] += a4.y * b4.y;
                        acc[1][2] += a4.y * b4.z; acc[1][3] += a4.y * b4.w;
                        acc[2][0] += a4.z * b4.x; acc[2][1] += a4.z * b4.y;
                        acc[2][2] += a4.z * b4.z; acc[2][3] += a4.z * b4.w;
                        acc[3][0] += a4.w * b4.x; acc[3][1] += a4.w * b4.y;
                        acc[3][2] += a4.w * b4.z; acc[3][3] += a4.w * b4.w;
                    }
                }

                const int j0 = c0 + tx * 4;
                const int i0 = r0 + ty * 4;
                #pragma unroll
                for (int m = 0; m < 4; ++m) {
                    float xs = __ldcg(&xsq[i0 + m]);
                    float e0 = __expf(-fmaxf(xs + __ldcg(&ysq[j0 + 0]) - 2.f * acc[m][0], 0.f) * (1.0f / REGC));
                    float e1 = __expf(-fmaxf(xs + __ldcg(&ysq[j0 + 1]) - 2.f * acc[m][1], 0.f) * (1.0f / REGC));
                    float e2 = __expf(-fmaxf(xs + __ldcg(&ysq[j0 + 2]) - 2.f * acc[m][2], 0.f) * (1.0f / REGC));
                    float e3 = __expf(-fmaxf(xs + __ldcg(&ysq[j0 + 3]) - 2.f * acc[m][3], 0.f) * (1.0f / REGC));
                    __nv_bfloat162 b01 = __floats2bfloat162_rn(e0, e1);
                    __nv_bfloat162 b23 = __floats2bfloat162_rn(e2, e3);
                    uint2 pk;
                    pk.x = *(unsigned int*)&b01;
                    pk.y = *(unsigned int*)&b23;
                    *(uint2*)(g_Kb + (size_t)(i0 + m) * NN + j0) = pk;
                }
            }
            if (tid < nrows) s_u[tid] = 1.0f;        // u is CTA-local
        }
        grid_barrier(gen, tid, bid);
        if (tid == 0) __threadfence();               // CCTL.IVALL: drop stale K lines
        __syncthreads();

        // ---------- Phase 3: NITER Sinkhorn iterations, K stripe L1-resident ----------
        for (int it = 0; it < NITER; ++it) {
            // (a) column partials over own rows: part[j] = sum_r K[rb+r, j] * u[r]
            {
                const int j0 = (wid << 7) + (lane << 2);      // warp: 128 cols
                float a0 = 0.f, a1 = 0.f, a2 = 0.f, a3 = 0.f;
                const int nl1 = (nrows < L1ROWS) ? nrows : L1ROWS;
                int r = 0;
                #pragma unroll 4
                for (; r < nl1; ++r) {
                    uint2 q = *(const uint2*)(g_Kb + (size_t)(rb + r) * NN + j0);
                    float ur = s_u[r];
                    a0 += bf_lo(q.x) * ur; a1 += bf_hi(q.x) * ur;
                    a2 += bf_lo(q.y) * ur; a3 += bf_hi(q.y) * ur;
                }
                for (; r < nrows; ++r) {
                    uint2 q = __ldcg((const uint2*)(g_Kb + (size_t)(rb + r) * NN + j0));
                    float ur = s_u[r];
                    a0 += bf_lo(q.x) * ur; a1 += bf_hi(q.x) * ur;
                    a2 += bf_lo(q.y) * ur; a3 += bf_hi(q.y) * ur;
                }
                *(float4*)(g_part + (size_t)bid * NN + j0) = make_float4(a0, a1, a2, a3);
            }
            grid_barrier(gen, tid, bid);

            // (b) v-reduce: CTA owns cols [rb,re) (same split); all 148 CTAs work
            {
                const int ncols = nrows;                    // reuse split
                float a = 0.f;
                if (lane < ncols) {
                    for (int c = wid; c < NBLK; c += NWARP)
                        a += __ldcg(&g_part[(size_t)c * NN + rb + lane]);
                }
                s_mem[wid * 36 + lane] = a;
                __syncthreads();
                if (wid == 0 && lane < ncols) {
                    float s = 0.f;
                    #pragma unroll
                    for (int w = 0; w < NWARP; ++w) s += s_mem[w * 36 + lane];
                    g_v[rb + lane] = MUNU / (s + EPSC);
                }
            }
            grid_barrier(gen, tid, bid);

            // (c) row pass: u[r] = MUNU / (dot(K[rb+r,:], v) + EPS) -> s_u (local)
            {
                const int gr = wid >> 3;                  // 4 groups x 7 rows
                const int jh = wid & 7;                   // 8 slices x 512 cols
                const int r0 = gr * 7;
                const int nr = nrows - r0;                // rows valid in this group

                const float4* v4 = (const float4*)g_v + jh * 128;
                float4 va0 = __ldcg(v4 + 2 * lane);
                float4 vb0 = __ldcg(v4 + 2 * lane + 1);
                float4 va1 = __ldcg(v4 + 2 * (lane + 32));
                float4 vb1 = __ldcg(v4 + 2 * (lane + 32) + 1);

                float acc[7];
                #pragma unroll
                for (int r = 0; r < 7; ++r) {
                    int ri = r0 + r;
                    ri = (ri < nrows) ? ri : (nrows - 1);     // clamp; discarded below
                    const uint4* kr = (const uint4*)(g_Kb + (size_t)(rb + ri) * NN) + jh * 64;
                    uint4 q0, q1;
                    if (ri < L1ROWS) { q0 = kr[lane]; q1 = kr[lane + 32]; }
                    else { q0 = __ldcg(kr + lane); q1 = __ldcg(kr + lane + 32); }
                    float a = dot8(q0, va0, vb0, 0.f);
                    acc[r] = dot8(q1, va1, vb1, a);
                }
                #pragma unroll
                for (int o = 16; o; o >>= 1) {
                    #pragma unroll
                    for (int r = 0; r < 7; ++r)
                        acc[r] += __shfl_xor_sync(0xffffffffu, acc[r], o);
                }
                if (lane == 0) {
                    #pragma unroll
                    for (int r = 0; r < 7; ++r)
                        if (r < nr) s_part[(r0 + r) * 9 + jh] = acc[r];
                }
                __syncthreads();
                if (tid < nrows) {
                    const float* pp = s_part + tid * 9;
                    float s = pp[0] + pp[1] + pp[2] + pp[3] + pp[4] + pp[5] + pp[6] + pp[7];
                    s_u[tid] = MUNU / (s + EPSC);
                }
                __syncthreads();
            }
            // no barrier: next col-partial needs only this CTA's own u
        }

        // ---------- Phase 4: loss += sum u_i K_ij v_j * (-REG * ln K_ij) ----------
        {
            const int gr = wid >> 3;
            const int jh = wid & 7;
            const int r0 = gr * 7;
            const int nr = nrows - r0;

            const float4* v4 = (const float4*)g_v + jh * 128;
            float4 va0 = __ldcg(v4 + 2 * lane);
            float4 vb0 = __ldcg(v4 + 2 * lane + 1);
            float4 va1 = __ldcg(v4 + 2 * (lane + 32));
            float4 vb1 = __ldcg(v4 + 2 * (lane + 32) + 1);

            float acc[7];
            #pragma unroll
            for (int r = 0; r < 7; ++r) {
                int ri = r0 + r;
                ri = (ri < nrows) ? ri : (nrows - 1);
                const uint4* kr = (const uint4*)(g_Kb + (size_t)(rb + ri) * NN) + jh * 64;
                uint4 q0 = kr[lane];
                uint4 q1 = kr[lane + 32];
                float a = 0.f, f;
                f = bf_lo(q0.x); a += f * va0.x * __logf(f);
                f = bf_hi(q0.x); a += f * va0.y * __logf(f);
                f = bf_lo(q0.y); a += f * va0.z * __logf(f);
                f = bf_hi(q0.y); a += f * va0.w * __logf(f);
                f = bf_lo(q0.z); a += f * vb0.x * __logf(f);
                f = bf_hi(q0.z); a += f * vb0.y * __logf(f);
                f = bf_lo(q0.w); a += f * vb0.z * __logf(f);
                f = bf_hi(q0.w); a += f * vb0.w * __logf(f);
                f = bf_lo(q1.x); a += f * va1.x * __logf(f);
                f = bf_hi(q1.x); a += f * va1.y * __logf(f);
                f = bf_lo(q1.y); a += f * va1.z * __logf(f);
                f = bf_hi(q1.y); a += f * va1.w * __logf(f);
                f = bf_lo(q1.z); a += f * vb1.x * __logf(f);
                f = bf_hi(q1.z); a += f * vb1.y * __logf(f);
                f = bf_lo(q1.w); a += f * vb1.z * __logf(f);
                f = bf_hi(q1.w); a += f * vb1.w * __logf(f);
                acc[r] = a;
            }
            #pragma unroll
            for (int o = 16; o; o >>= 1) {
                #pragma unroll
                for (int r = 0; r < 7; ++r)
                    acc[r] += __shfl_xor_sync(0xffffffffu, acc[r], o);
            }
            if (lane == 0) {
                #pragma unroll
                for (int r = 0; r < 7; ++r)
                    if (r < nr) s_part[(r0 + r) * 9 + jh] = acc[r];
            }
            __syncthreads();
            if (tid < nrows) {
                const float* pp = s_part + tid * 9;
                float tot = pp[0] + pp[1] + pp[2] + pp[3] + pp[4] + pp[5] + pp[6] + pp[7];
                s_dval[tid] = (double)s_u[tid] * (double)tot;
            }
            __syncthreads();
            if (tid == 0) {
                double c = 0.0;
                for (int i = 0; i < nrows; ++i) c += s_dval[i];
                atomicAdd(&g_loss, (double)(-REGC) * c);
            }
        }
        grid_barrier(gen, tid, bid);   // protect Kb/g_v before next pair overwrites
    }

    if (bid == 0 && tid == 0) {
        double l;
        asm volatile("ld.global.cg.f64 %0, [%1];" : "=d"(l) : "l"(&g_loss));
        out[0] = (float)(l / 3.0);
    }
}

extern "C" void kernel_launch(void* const* d_in, const int* in_sizes, int n_in,
                              void* d_out, int out_size) {
    (void)in_sizes; (void)n_in; (void)out_size;
    const float* z0 = (const float*)d_in[0];
    const float* z1 = (const float*)d_in[1];
    const float* z2 = (const float*)d_in[2];
    ot_kernel<<<NBLK, NTHR>>>(z0, z1, z2, (float*)d_out);
}

// round 14
// speedup vs baseline: 1.0046x; 1.0046x over previous
#include <cuda_runtime.h>
#include <cuda_bf16.h>

#define NN 4096
#define DD 128
#define NBLK 148
#define NTHR 1024
#define NWARP 32
#define REGC 0.05f
#define EPSC 1e-8f
#define NITER 9
#define MUNU (1.0f / 4096.0f)
#define L1ROWS 22            // rows kept L1-resident per CTA (176KB of ~210KB L1D)

// Scratch (__device__ globals — sanctioned)
__device__ __nv_bfloat16 g_Kb[(size_t)NN * NN];   // bf16 K row-major (only copy)
__device__ float g_part[(size_t)NBLK * NN];       // per-CTA partial column sums
__device__ float g_v[NN];
__device__ float g_nsq[3 * NN];
__device__ double g_loss;
__device__ unsigned int g_flags[NBLK * 64];       // 256B-strided slot per CTA
__device__ unsigned int g_bar_gen;

__device__ __forceinline__ float bf_lo(unsigned int u) { return __uint_as_float(u << 16); }
__device__ __forceinline__ float bf_hi(unsigned int u) { return __uint_as_float(u & 0xffff0000u); }

__device__ __forceinline__ unsigned int ld_acq(const unsigned int* p) {
    unsigned int v;
    asm volatile("ld.acquire.gpu.global.u32 %0, [%1];" : "=r"(v) : "l"(p) : "memory");
    return v;
}
__device__ __forceinline__ void st_rel(unsigned int* p, unsigned int v) {
    asm volatile("st.release.gpu.global.u32 [%0], %1;" :: "l"(p), "r"(v) : "memory");
}

// Fence-free 2-hop grid barrier (one writer + ONE poller per flag line — no
// poll contention). CTA0's threads each poll a distinct 256B-strided slot,
// then CTA0 releases g_bar_gen, which every other CTA's tid0 polls.
// Cross-barrier mutable data is read .cg; K is write-once + IVALL per pair.
__device__ __forceinline__ void grid_barrier(unsigned int& gen, int tid, int bid) {
    __syncthreads();
    ++gen;
    if (bid == 0) {
        if (tid == 0) st_rel(&g_flags[0], gen);
        if (tid > 0 && tid < NBLK) {
            const unsigned int* f = &g_flags[tid * 64];
            while ((int)(ld_acq(f) - gen) < 0) { }
        }
        __syncthreads();                       // all 148 arrivals observed+acquired
        if (tid == 0) st_rel(&g_bar_gen, gen);
    } else {
        if (tid == 0) {
            st_rel(&g_flags[bid * 64], gen);
            while ((int)(ld_acq(&g_bar_gen) - gen) < 0) { }
        }
        __syncthreads();
    }
}

__device__ __forceinline__ float dot8(uint4 q, float4 va, float4 vb, float acc) {
    acc += bf_lo(q.x) * va.x + bf_hi(q.x) * va.y
         + bf_lo(q.y) * va.z + bf_hi(q.y) * va.w
         + bf_lo(q.z) * vb.x + bf_hi(q.z) * vb.y
         + bf_lo(q.w) * vb.z + bf_hi(q.w) * vb.w;
    return acc;
}

__global__ __launch_bounds__(NTHR, 1) void ot_kernel(
    const float* __restrict__ z0, const float* __restrict__ z1,
    const float* __restrict__ z2, float* __restrict__ out)
{
    // s_mem: GEMM tiles (2 x 16x132 floats = 16.9KB) / v-reduce scratch overlay
    __shared__ __align__(16) float s_mem[2 * 16 * 132];
    __shared__ float s_part[28 * 9];
    __shared__ float s_u[28];
    __shared__ double s_dval[28];

    const int tid  = threadIdx.x;
    const int bid  = blockIdx.x;
    const int wid  = tid >> 5;
    const int lane = tid & 31;
    const int rb    = (int)(((long long)bid * NN) / NBLK);
    const int re    = (int)(((long long)(bid + 1) * NN) / NBLK);
    const int nrows = re - rb;                      // 27 or 28

    unsigned int gen = __ldcg(&g_bar_gen);          // monotonic across graph replays

    if (bid == 0 && tid == 0) g_loss = 0.0;

    const float* Z[3] = { z0, z1, z2 };
    const int XI[3] = { 0, 0, 1 };
    const int YI[3] = { 1, 2, 2 };

    // ---------- Phase 0 (once): row norms of z0,z1,z2 ----------
    for (int r = bid * NWARP + wid; r < 3 * NN; r += NBLK * NWARP) {
        const float* src = Z[r >> 12];
        int row = r & (NN - 1);
        float4 v4 = ((const float4*)(src + (size_t)row * DD))[lane];
        float s = v4.x * v4.x + v4.y * v4.y + v4.z * v4.z + v4.w * v4.w;
        #pragma unroll
        for (int o = 16; o; o >>= 1) s += __shfl_xor_sync(0xffffffffu, s, o);
        if (lane == 0) g_nsq[r] = s;
    }
    grid_barrier(gen, tid, bid);

    for (int pr = 0; pr < 3; ++pr) {
        const float* x = Z[XI[pr]];
        const float* y = Z[YI[pr]];
        const float* xsq = g_nsq + XI[pr] * NN;
        const float* ysq = g_nsq + YI[pr] * NN;

        // ---------- Phase 2: K = exp(-C/REG) -> Kb (row-major only); u := 1 ----------
        {
            float* sxT = s_mem;                  // [16 k][128 i], stride 132
            float* syT = s_mem + 16 * 132;       // [16 k][128 j], stride 132
            const int ty = tid >> 5;             // 0..31 -> 4 rows each
            const int tx = tid & 31;             // 0..31 -> 4 cols each
            const int NT = (NN / 128) * (NN / 128);   // 1024 tiles

            for (int t = bid; t < NT; t += NBLK) {
                const int r0 = (t >> 5) * 128;
                const int c0 = (t & 31) * 128;
                float acc[4][4];
                #pragma unroll
                for (int m = 0; m < 4; ++m)
                    #pragma unroll
                    for (int n = 0; n < 4; ++n) acc[m][n] = 0.f;

                for (int kc = 0; kc < DD; kc += 16) {
                    __syncthreads();
                    #pragma unroll
                    for (int idx = tid; idx < 128 * 16; idx += NTHR) {
                        int rr = idx >> 4, cc = idx & 15;
                        sxT[cc * 132 + rr] = x[(size_t)(r0 + rr) * DD + kc + cc];
                        syT[cc * 132 + rr] = y[(size_t)(c0 + rr) * DD + kc + cc];
                    }
                    __syncthreads();
                    #pragma unroll
                    for (int k = 0; k < 16; ++k) {
                        float4 a4 = *(const float4*)&sxT[k * 132 + ty * 4];
                        float4 b4 = *(const float4*)&syT[k * 132 + tx * 4];
                        acc[0][0] += a4.x * b4.x; acc[0][1] += a4.x * b4.y;
                        acc[0][2] += a4.x * b4.z; acc[0][3] += a4.x * b4.w;
                        acc[1][0] += a4.y * b4.x; acc[1][1] += a4.y * b4.y;
                        acc[1][2] += a4.y * b4.z; acc[1][3] += a4.y * b4.w;
                        acc[2][0] += a4.z * b4.x; acc[2][1] += a4.z * b4.y;
                        acc[2][2] += a4.z * b4.z; acc[2][3] += a4.z * b4.w;
                        acc[3][0] += a4.w * b4.x; acc[3][1] += a4.w * b4.y;
                        acc[3][2] += a4.w * b4.z; acc[3][3] += a4.w * b4.w;
                    }
                }

                const int j0 = c0 + tx * 4;
                const int i0 = r0 + ty * 4;
                #pragma unroll
                for (int m = 0; m < 4; ++m) {
                    float xs = __ldcg(&xsq[i0 + m]);
                    float e0 = __expf(-fmaxf(xs + __ldcg(&ysq[j0 + 0]) - 2.f * acc[m][0], 0.f) * (1.0f / REGC));
                    float e1 = __expf(-fmaxf(xs + __ldcg(&ysq[j0 + 1]) - 2.f * acc[m][1], 0.f) * (1.0f / REGC));
                    float e2 = __expf(-fmaxf(xs + __ldcg(&ysq[j0 + 2]) - 2.f * acc[m][2], 0.f) * (1.0f / REGC));
                    float e3 = __expf(-fmaxf(xs + __ldcg(&ysq[j0 + 3]) - 2.f * acc[m][3], 0.f) * (1.0f / REGC));
                    __nv_bfloat162 b01 = __floats2bfloat162_rn(e0, e1);
                    __nv_bfloat162 b23 = __floats2bfloat162_rn(e2, e3);
                    uint2 pk;
                    pk.x = *(unsigned int*)&b01;
                    pk.y = *(unsigned int*)&b23;
                    *(uint2*)(g_Kb + (size_t)(i0 + m) * NN + j0) = pk;
                }
            }
            if (tid < nrows) s_u[tid] = 1.0f;        // u is CTA-local
        }
        grid_barrier(gen, tid, bid);
        if (tid == 0) __threadfence();               // CCTL.IVALL: drop stale K lines
        __syncthreads();

        // ---------- Phase 3: NITER Sinkhorn iterations, K stripe L1-resident ----------
        for (int it = 0; it < NITER; ++it) {
            // (a) column partials over own rows: part[j] = sum_r K[rb+r, j] * u[r]
            {
                const int j0 = (wid << 7) + (lane << 2);      // warp: 128 cols
                float a0 = 0.f, a1 = 0.f, a2 = 0.f, a3 = 0.f;
                const int nl1 = (nrows < L1ROWS) ? nrows : L1ROWS;
                int r = 0;
                #pragma unroll 4
                for (; r < nl1; ++r) {
                    uint2 q = *(const uint2*)(g_Kb + (size_t)(rb + r) * NN + j0);
                    float ur = s_u[r];
                    a0 += bf_lo(q.x) * ur; a1 += bf_hi(q.x) * ur;
                    a2 += bf_lo(q.y) * ur; a3 += bf_hi(q.y) * ur;
                }
                for (; r < nrows; ++r) {
                    uint2 q = __ldcg((const uint2*)(g_Kb + (size_t)(rb + r) * NN + j0));
                    float ur = s_u[r];
                    a0 += bf_lo(q.x) * ur; a1 += bf_hi(q.x) * ur;
                    a2 += bf_lo(q.y) * ur; a3 += bf_hi(q.y) * ur;
                }
                *(float4*)(g_part + (size_t)bid * NN + j0) = make_float4(a0, a1, a2, a3);
            }
            grid_barrier(gen, tid, bid);

            // (b) v-reduce: CTA owns cols [rb,re) (same split); all 148 CTAs work
            {
                const int ncols = nrows;                    // reuse split
                float a = 0.f;
                if (lane < ncols) {
                    for (int c = wid; c < NBLK; c += NWARP)
                        a += __ldcg(&g_part[(size_t)c * NN + rb + lane]);
                }
                s_mem[wid * 36 + lane] = a;
                __syncthreads();
                if (wid == 0 && lane < ncols) {
                    float s = 0.f;
                    #pragma unroll
                    for (int w = 0; w < NWARP; ++w) s += s_mem[w * 36 + lane];
                    g_v[rb + lane] = MUNU / (s + EPSC);
                }
            }
            grid_barrier(gen, tid, bid);

            // (c) row pass: u[r] = MUNU / (dot(K[rb+r,:], v) + EPS) -> s_u (local)
            {
                const int gr = wid >> 3;                  // 4 groups x 7 rows
                const int jh = wid & 7;                   // 8 slices x 512 cols
                const int r0 = gr * 7;
                const int nr = nrows - r0;                // rows valid in this group

                const float4* v4 = (const float4*)g_v + jh * 128;
                float4 va0 = __ldcg(v4 + 2 * lane);
                float4 vb0 = __ldcg(v4 + 2 * lane + 1);
                float4 va1 = __ldcg(v4 + 2 * (lane + 32));
                float4 vb1 = __ldcg(v4 + 2 * (lane + 32) + 1);

                float acc[7];
                #pragma unroll
                for (int r = 0; r < 7; ++r) {
                    int ri = r0 + r;
                    ri = (ri < nrows) ? ri : (nrows - 1);     // clamp; discarded below
                    const uint4* kr = (const uint4*)(g_Kb + (size_t)(rb + ri) * NN) + jh * 64;
                    uint4 q0, q1;
                    if (ri < L1ROWS) { q0 = kr[lane]; q1 = kr[lane + 32]; }
                    else { q0 = __ldcg(kr + lane); q1 = __ldcg(kr + lane + 32); }
                    float a = dot8(q0, va0, vb0, 0.f);
                    acc[r] = dot8(q1, va1, vb1, a);
                }
                #pragma unroll
                for (int o = 16; o; o >>= 1) {
                    #pragma unroll
                    for (int r = 0; r < 7; ++r)
                        acc[r] += __shfl_xor_sync(0xffffffffu, acc[r], o);
                }
                if (lane == 0) {
                    #pragma unroll
                    for (int r = 0; r < 7; ++r)
                        if (r < nr) s_part[(r0 + r) * 9 + jh] = acc[r];
                }
                __syncthreads();
                if (tid < nrows) {
                    const float* pp = s_part + tid * 9;
                    float s = pp[0] + pp[1] + pp[2] + pp[3] + pp[4] + pp[5] + pp[6] + pp[7];
                    s_u[tid] = MUNU / (s + EPSC);
                }
                __syncthreads();
            }
            // no barrier: next col-partial needs only this CTA's own u
        }

        // ---------- Phase 4: loss += sum u_i K_ij v_j * (-REG * ln K_ij) ----------
        {
            const int gr = wid >> 3;
            const int jh = wid & 7;
            const int r0 = gr * 7;
            const int nr = nrows - r0;

            const float4* v4 = (const float4*)g_v + jh * 128;
            float4 va0 = __ldcg(v4 + 2 * lane);
            float4 vb0 = __ldcg(v4 + 2 * lane + 1);
            float4 va1 = __ldcg(v4 + 2 * (lane + 32));
            float4 vb1 = __ldcg(v4 + 2 * (lane + 32) + 1);

            float acc[7];
            #pragma unroll
            for (int r = 0; r < 7; ++r) {
                int ri = r0 + r;
                ri = (ri < nrows) ? ri : (nrows - 1);
                const uint4* kr = (const uint4*)(g_Kb + (size_t)(rb + ri) * NN) + jh * 64;
                uint4 q0 = kr[lane];
                uint4 q1 = kr[lane + 32];
                float a = 0.f, f;
                f = bf_lo(q0.x); a += f * va0.x * __logf(f);
                f = bf_hi(q0.x); a += f * va0.y * __logf(f);
                f = bf_lo(q0.y); a += f * va0.z * __logf(f);
                f = bf_hi(q0.y); a += f * va0.w * __logf(f);
                f = bf_lo(q0.z); a += f * vb0.x * __logf(f);
                f = bf_hi(q0.z); a += f * vb0.y * __logf(f);
                f = bf_lo(q0.w); a += f * vb0.z * __logf(f);
                f = bf_hi(q0.w); a += f * vb0.w * __logf(f);
                f = bf_lo(q1.x); a += f * va1.x * __logf(f);
                f = bf_hi(q1.x); a += f * va1.y * __logf(f);
                f = bf_lo(q1.y); a += f * va1.z * __logf(f);
                f = bf_hi(q1.y); a += f * va1.w * __logf(f);
                f = bf_lo(q1.z); a += f * vb1.x * __logf(f);
                f = bf_hi(q1.z); a += f * vb1.y * __logf(f);
                f = bf_lo(q1.w); a += f * vb1.z * __logf(f);
                f = bf_hi(q1.w); a += f * vb1.w * __logf(f);
                acc[r] = a;
            }
            #pragma unroll
            for (int o = 16; o; o >>= 1) {
                #pragma unroll
                for (int r = 0; r < 7; ++r)
                    acc[r] += __shfl_xor_sync(0xffffffffu, acc[r], o);
            }
            if (lane == 0) {
                #pragma unroll
                for (int r = 0; r < 7; ++r)
                    if (r < nr) s_part[(r0 + r) * 9 + jh] = acc[r];
            }
            __syncthreads();
            if (tid < nrows) {
                const float* pp = s_part + tid * 9;
                float tot = pp[0] + pp[1] + pp[2] + pp[3] + pp[4] + pp[5] + pp[6] + pp[7];
                s_dval[tid] = (double)s_u[tid] * (double)tot;
            }
            __syncthreads();
            if (tid == 0) {
                double c = 0.0;
                for (int i = 0; i < nrows; ++i) c += s_dval[i];
                atomicAdd(&g_loss, (double)(-REGC) * c);
            }
        }
        grid_barrier(gen, tid, bid);   // protect Kb/g_v before next pair overwrites
    }

    if (bid == 0 && tid == 0) {
        double l;
        asm volatile("ld.global.cg.f64 %0, [%1];" : "=d"(l) : "l"(&g_loss));
        out[0] = (float)(l / 3.0);
    }
}

extern "C" void kernel_launch(void* const* d_in, const int* in_sizes, int n_in,
                              void* d_out, int out_size) {
    (void)in_sizes; (void)n_in; (void)out_size;
    const float* z0 = (const float*)d_in[0];
    const float* z1 = (const float*)d_in[1];
    const float* z2 = (const float*)d_in[2];
    ot_kernel<<<NBLK, NTHR>>>(z0, z1, z2, (float*)d_out);
}

// round 15
// speedup vs baseline: 1.4550x; 1.4484x over previous
#include <cuda_runtime.h>
#include <cuda_bf16.h>

#define NN 4096
#define DD 128
#define NBLK 148
#define NTHR 1024
#define NWARP 32
#define REGC 0.05f
#define EPSC 1e-8f
#define NITER 9
#define MUNU (1.0f / 4096.0f)
#define L1ROWS 22            // rows kept L1-resident per CTA (176KB of ~210KB L1D)

// Scratch (__device__ globals — sanctioned)
__device__ __nv_bfloat16 g_Kb[(size_t)NN * NN];   // bf16 K row-major (only copy)
__device__ float g_part[(size_t)NBLK * NN];       // per-CTA partial column sums
__device__ float g_v[NN];
__device__ float g_nsq[3 * NN];
__device__ double g_loss;
__device__ unsigned int g_flags[NBLK * 64];       // 256B-strided slot per CTA
__device__ unsigned int g_bar_gen;

__device__ __forceinline__ float bf_lo(unsigned int u) { return __uint_as_float(u << 16); }
__device__ __forceinline__ float bf_hi(unsigned int u) { return __uint_as_float(u & 0xffff0000u); }

__device__ __forceinline__ unsigned int ld_acq(const unsigned int* p) {
    unsigned int v;
    asm volatile("ld.acquire.gpu.global.u32 %0, [%1];" : "=r"(v) : "l"(p) : "memory");
    return v;
}
__device__ __forceinline__ void st_rel(unsigned int* p, unsigned int v) {
    asm volatile("st.release.gpu.global.u32 [%0], %1;" :: "l"(p), "r"(v) : "memory");
}

// Fence-free 2-hop grid barrier (one writer + ONE poller per flag line — no
// poll contention). CTA0's threads each poll a distinct 256B-strided slot,
// then CTA0 releases g_bar_gen, which every other CTA's tid0 polls.
// Cross-barrier mutable data is read .cg; K is write-once + IVALL per pair.
__device__ __forceinline__ void grid_barrier(unsigned int& gen, int tid, int bid) {
    __syncthreads();
    ++gen;
    if (bid == 0) {
        if (tid == 0) st_rel(&g_flags[0], gen);
        if (tid > 0 && tid < NBLK) {
            const unsigned int* f = &g_flags[tid * 64];
            while ((int)(ld_acq(f) - gen) < 0) { }
        }
        __syncthreads();                       // all 148 arrivals observed+acquired
        if (tid == 0) st_rel(&g_bar_gen, gen);
    } else {
        if (tid == 0) {
            st_rel(&g_flags[bid * 64], gen);
            while ((int)(ld_acq(&g_bar_gen) - gen) < 0) { }
        }
        __syncthreads();
    }
}

__device__ __forceinline__ float dot8(uint4 q, float4 va, float4 vb, float acc) {
    acc += bf_lo(q.x) * va.x + bf_hi(q.x) * va.y
         + bf_lo(q.y) * va.z + bf_hi(q.y) * va.w
         + bf_lo(q.z) * vb.x + bf_hi(q.z) * vb.y
         + bf_lo(q.w) * vb.z + bf_hi(q.w) * vb.w;
    return acc;
}

__global__ __launch_bounds__(NTHR, 1) void ot_kernel(
    const float* __restrict__ z0, const float* __restrict__ z1,
    const float* __restrict__ z2, float* __restrict__ out)
{
    // s_mem: GEMM tiles (2 x 16x132 floats = 16.9KB) / v-reduce scratch overlay
    __shared__ __align__(16) float s_mem[2 * 16 * 132];
    __shared__ float s_part[28 * 9];
    __shared__ float s_u[28];
    __shared__ double s_dval[28];

    const int tid  = threadIdx.x;
    const int bid  = blockIdx.x;
    const int wid  = tid >> 5;
    const int lane = tid & 31;
    const int rb    = (int)(((long long)bid * NN) / NBLK);
    const int re    = (int)(((long long)(bid + 1) * NN) / NBLK);
    const int nrows = re - rb;                      // 27 or 28

    unsigned int gen = __ldcg(&g_bar_gen);          // monotonic across graph replays

    if (bid == 0 && tid == 0) g_loss = 0.0;

    const float* Z[3] = { z0, z1, z2 };
    const int XI[3] = { 0, 0, 1 };
    const int YI[3] = { 1, 2, 2 };

    // ---------- Phase 0 (once): row norms of z0,z1,z2 ----------
    for (int r = bid * NWARP + wid; r < 3 * NN; r += NBLK * NWARP) {
        const float* src = Z[r >> 12];
        int row = r & (NN - 1);
        float4 v4 = ((const float4*)(src + (size_t)row * DD))[lane];
        float s = v4.x * v4.x + v4.y * v4.y + v4.z * v4.z + v4.w * v4.w;
        #pragma unroll
        for (int o = 16; o; o >>= 1) s += __shfl_xor_sync(0xffffffffu, s, o);
        if (lane == 0) g_nsq[r] = s;
    }
    grid_barrier(gen, tid, bid);

    #pragma unroll 1
    for (int pr = 0; pr < 3; ++pr) {
        const float* x = Z[XI[pr]];
        const float* y = Z[YI[pr]];
        const float* xsq = g_nsq + XI[pr] * NN;
        const float* ysq = g_nsq + YI[pr] * NN;

        // ---------- Phase 2: K = exp(-C/REG) -> Kb (row-major only); u := 1 ----------
        {
            float* sxT = s_mem;                  // [16 k][128 i], stride 132
            float* syT = s_mem + 16 * 132;       // [16 k][128 j], stride 132
            const int ty = tid >> 5;             // 0..31 -> 4 rows each
            const int tx = tid & 31;             // 0..31 -> 4 cols each
            const int NT = (NN / 128) * (NN / 128);   // 1024 tiles

            #pragma unroll 1
            for (int t = bid; t < NT; t += NBLK) {
                const int r0 = (t >> 5) * 128;
                const int c0 = (t & 31) * 128;
                float acc[4][4];
                #pragma unroll
                for (int m = 0; m < 4; ++m)
                    #pragma unroll
                    for (int n = 0; n < 4; ++n) acc[m][n] = 0.f;

                #pragma unroll 1
                for (int kc = 0; kc < DD; kc += 16) {
                    __syncthreads();
                    #pragma unroll
                    for (int idx = tid; idx < 128 * 16; idx += NTHR) {
                        int rr = idx >> 4, cc = idx & 15;
                        sxT[cc * 132 + rr] = x[(size_t)(r0 + rr) * DD + kc + cc];
                        syT[cc * 132 + rr] = y[(size_t)(c0 + rr) * DD + kc + cc];
                    }
                    __syncthreads();
                    #pragma unroll
                    for (int k = 0; k < 16; ++k) {
                        float4 a4 = *(const float4*)&sxT[k * 132 + ty * 4];
                        float4 b4 = *(const float4*)&syT[k * 132 + tx * 4];
                        acc[0][0] += a4.x * b4.x; acc[0][1] += a4.x * b4.y;
                        acc[0][2] += a4.x * b4.z; acc[0][3] += a4.x * b4.w;
                        acc[1][0] += a4.y * b4.x; acc[1][1] += a4.y * b4.y;
                        acc[1][2] += a4.y * b4.z; acc[1][3] += a4.y * b4.w;
                        acc[2][0] += a4.z * b4.x; acc[2][1] += a4.z * b4.y;
                        acc[2][2] += a4.z * b4.z; acc[2][3] += a4.z * b4.w;
                        acc[3][0] += a4.w * b4.x; acc[3][1] += a4.w * b4.y;
                        acc[3][2] += a4.w * b4.z; acc[3][3] += a4.w * b4.w;
                    }
                }

                const int j0 = c0 + tx * 4;
                const int i0 = r0 + ty * 4;
                #pragma unroll
                for (int m = 0; m < 4; ++m) {
                    float xs = __ldcg(&xsq[i0 + m]);
                    float e0 = __expf(-fmaxf(xs + __ldcg(&ysq[j0 + 0]) - 2.f * acc[m][0], 0.f) * (1.0f / REGC));
                    float e1 = __expf(-fmaxf(xs + __ldcg(&ysq[j0 + 1]) - 2.f * acc[m][1], 0.f) * (1.0f / REGC));
                    float e2 = __expf(-fmaxf(xs + __ldcg(&ysq[j0 + 2]) - 2.f * acc[m][2], 0.f) * (1.0f / REGC));
                    float e3 = __expf(-fmaxf(xs + __ldcg(&ysq[j0 + 3]) - 2.f * acc[m][3], 0.f) * (1.0f / REGC));
                    __nv_bfloat162 b01 = __floats2bfloat162_rn(e0, e1);
                    __nv_bfloat162 b23 = __floats2bfloat162_rn(e2, e3);
                    uint2 pk;
                    pk.x = *(unsigned int*)&b01;
                    pk.y = *(unsigned int*)&b23;
                    *(uint2*)(g_Kb + (size_t)(i0 + m) * NN + j0) = pk;
                }
            }
            if (tid < nrows) s_u[tid] = 1.0f;        // u is CTA-local
        }
        grid_barrier(gen, tid, bid);
        if (tid == 0) __threadfence();               // CCTL.IVALL: drop stale K lines
        __syncthreads();

        // ---------- Phase 3: NITER Sinkhorn iterations, K stripe L1-resident ----------
        #pragma unroll 1
        for (int it = 0; it < NITER; ++it) {
            // (a) column partials over own rows: part[j] = sum_r K[rb+r, j] * u[r]
            {
                const int j0 = (wid << 7) + (lane << 2);      // warp: 128 cols
                float a0 = 0.f, a1 = 0.f, a2 = 0.f, a3 = 0.f;
                const int nl1 = (nrows < L1ROWS) ? nrows : L1ROWS;
                int r = 0;
                #pragma unroll 4
                for (; r < nl1; ++r) {
                    uint2 q = *(const uint2*)(g_Kb + (size_t)(rb + r) * NN + j0);
                    float ur = s_u[r];
                    a0 += bf_lo(q.x) * ur; a1 += bf_hi(q.x) * ur;
                    a2 += bf_lo(q.y) * ur; a3 += bf_hi(q.y) * ur;
                }
                #pragma unroll 1
                for (; r < nrows; ++r) {
                    uint2 q = __ldcg((const uint2*)(g_Kb + (size_t)(rb + r) * NN + j0));
                    float ur = s_u[r];
                    a0 += bf_lo(q.x) * ur; a1 += bf_hi(q.x) * ur;
                    a2 += bf_lo(q.y) * ur; a3 += bf_hi(q.y) * ur;
                }
                *(float4*)(g_part + (size_t)bid * NN + j0) = make_float4(a0, a1, a2, a3);
            }
            grid_barrier(gen, tid, bid);

            // (b) v-reduce: CTA owns cols [rb,re) (same split); all 148 CTAs work
            {
                const int ncols = nrows;                    // reuse split
                float a = 0.f;
                if (lane < ncols) {
                    #pragma unroll 1
                    for (int c = wid; c < NBLK; c += NWARP)
                        a += __ldcg(&g_part[(size_t)c * NN + rb + lane]);
                }
                s_mem[wid * 36 + lane] = a;
                __syncthreads();
                if (wid == 0 && lane < ncols) {
                    float s = 0.f;
                    #pragma unroll
                    for (int w = 0; w < NWARP; ++w) s += s_mem[w * 36 + lane];
                    g_v[rb + lane] = MUNU / (s + EPSC);
                }
            }
            grid_barrier(gen, tid, bid);

            // (c) row pass: u[r] = MUNU / (dot(K[rb+r,:], v) + EPS) -> s_u (local)
            {
                const int gr = wid >> 3;                  // 4 groups x 7 rows
                const int jh = wid & 7;                   // 8 slices x 512 cols
                const int r0 = gr * 7;
                const int nr = nrows - r0;                // rows valid in this group

                const float4* v4 = (const float4*)g_v + jh * 128;
                float4 va0 = __ldcg(v4 + 2 * lane);
                float4 vb0 = __ldcg(v4 + 2 * lane + 1);
                float4 va1 = __ldcg(v4 + 2 * (lane + 32));
                float4 vb1 = __ldcg(v4 + 2 * (lane + 32) + 1);

                float acc[7];
                #pragma unroll
                for (int r = 0; r < 7; ++r) {
                    int ri = r0 + r;
                    ri = (ri < nrows) ? ri : (nrows - 1);     // clamp; discarded below
                    const uint4* kr = (const uint4*)(g_Kb + (size_t)(rb + ri) * NN) + jh * 64;
                    uint4 q0, q1;
                    if (ri < L1ROWS) { q0 = kr[lane]; q1 = kr[lane + 32]; }
                    else { q0 = __ldcg(kr + lane); q1 = __ldcg(kr + lane + 32); }
                    float a = dot8(q0, va0, vb0, 0.f);
                    acc[r] = dot8(q1, va1, vb1, a);
                }
                #pragma unroll
                for (int o = 16; o; o >>= 1) {
                    #pragma unroll
                    for (int r = 0; r < 7; ++r)
                        acc[r] += __shfl_xor_sync(0xffffffffu, acc[r], o);
                }
                if (lane == 0) {
                    #pragma unroll
                    for (int r = 0; r < 7; ++r)
                        if (r < nr) s_part[(r0 + r) * 9 + jh] = acc[r];
                }
                __syncthreads();
                if (tid < nrows) {
                    const float* pp = s_part + tid * 9;
                    float s = pp[0] + pp[1] + pp[2] + pp[3] + pp[4] + pp[5] + pp[6] + pp[7];
                    s_u[tid] = MUNU / (s + EPSC);
                }
                __syncthreads();
            }
            // no barrier: next col-partial needs only this CTA's own u
        }

        // ---------- Phase 4: loss += sum u_i K_ij v_j * (-REG * ln K_ij) ----------
        {
            const int gr = wid >> 3;
            const int jh = wid & 7;
            const int r0 = gr * 7;
            const int nr = nrows - r0;

            const float4* v4 = (const float4*)g_v + jh * 128;
            float4 va0 = __ldcg(v4 + 2 * lane);
            float4 vb0 = __ldcg(v4 + 2 * lane + 1);
            float4 va1 = __ldcg(v4 + 2 * (lane + 32));
            float4 vb1 = __ldcg(v4 + 2 * (lane + 32) + 1);

            float acc[7];
            #pragma unroll 1
            for (int r = 0; r < 7; ++r) {
                int ri = r0 + r;
                ri = (ri < nrows) ? ri : (nrows - 1);
                const uint4* kr = (const uint4*)(g_Kb + (size_t)(rb + ri) * NN) + jh * 64;
                uint4 q0 = kr[lane];
                uint4 q1 = kr[lane + 32];
                float a = 0.f, f;
                f = bf_lo(q0.x); a += f * va0.x * __logf(f);
                f = bf_hi(q0.x); a += f * va0.y * __logf(f);
                f = bf_lo(q0.y); a += f * va0.z * __logf(f);
                f = bf_hi(q0.y); a += f * va0.w * __logf(f);
                f = bf_lo(q0.z); a += f * vb0.x * __logf(f);
                f = bf_hi(q0.z); a += f * vb0.y * __logf(f);
                f = bf_lo(q0.w); a += f * vb0.z * __logf(f);
                f = bf_hi(q0.w); a += f * vb0.w * __logf(f);
                f = bf_lo(q1.x); a += f * va1.x * __logf(f);
                f = bf_hi(q1.x); a += f * va1.y * __logf(f);
                f = bf_lo(q1.y); a += f * va1.z * __logf(f);
                f = bf_hi(q1.y); a += f * va1.w * __logf(f);
                f = bf_lo(q1.z); a += f * vb1.x * __logf(f);
                f = bf_hi(q1.z); a += f * vb1.y * __logf(f);
                f = bf_lo(q1.w); a += f * vb1.z * __logf(f);
                f = bf_hi(q1.w); a += f * vb1.w * __logf(f);
                acc[r] = a;
            }
            #pragma unroll
            for (int o = 16; o; o >>= 1) {
                #pragma unroll
                for (int r = 0; r < 7; ++r)
                    acc[r] += __shfl_xor_sync(0xffffffffu, acc[r], o);
            }
            if (lane == 0) {
                #pragma unroll
                for (int r = 0; r < 7; ++r)
                    if (r < nr) s_part[(r0 + r) * 9 + jh] = acc[r];
            }
            __syncthreads();
            if (tid < nrows) {
                const float* pp = s_part + tid * 9;
                float tot = pp[0] + pp[1] + pp[2] + pp[3] + pp[4] + pp[5] + pp[6] + pp[7];
                s_dval[tid] = (double)s_u[tid] * (double)tot;
            }
            __syncthreads();
            if (tid == 0) {
                double c = 0.0;
                for (int i = 0; i < nrows; ++i) c += s_dval[i];
                atomicAdd(&g_loss, (double)(-REGC) * c);
            }
        }
        grid_barrier(gen, tid, bid);   // protect Kb/g_v before next pair overwrites
    }

    if (bid == 0 && tid == 0) {
        double l;
        asm volatile("ld.global.cg.f64 %0, [%1];" : "=d"(l) : "l"(&g_loss));
        out[0] = (float)(l / 3.0);
    }
}

extern "C" void kernel_launch(void* const* d_in, const int* in_sizes, int n_in,
                              void* d_out, int out_size) {
    (void)in_sizes; (void)n_in; (void)out_size;
    const float* z0 = (const float*)d_in[0];
    const float* z1 = (const float*)d_in[1];
    const float* z2 = (const float*)d_in[2];
    ot_kernel<<<NBLK, NTHR>>>(z0, z1, z2, (float*)d_out);
}

// round 16
// speedup vs baseline: 2.0415x; 1.4031x over previous
#include <cuda_runtime.h>
#include <cuda_bf16.h>

#define NN 4096
#define DD 128
#define NBLK 148
#define NTHR 1024
#define NWARP 32
#define REGC 0.05f
#define EPSC 1e-8f
#define NITER 9
#define MUNU (1.0f / 4096.0f)
#define L1ROWS 22            // rows kept L1-resident per CTA (176KB of ~210KB L1D)

// Scratch (__device__ globals — sanctioned)
__device__ __nv_bfloat16 g_Kb[(size_t)NN * NN];   // bf16 K row-major (only copy)
__device__ float g_part[(size_t)NBLK * NN];       // per-CTA partial column sums
__device__ float g_v[NN];
__device__ float g_nsq[3 * NN];
__device__ double g_loss;
__device__ unsigned int g_flags[NBLK * 64];       // 256B-strided slot per CTA
__device__ unsigned int g_bar_gen;

__device__ __forceinline__ float bf_lo(unsigned int u) { return __uint_as_float(u << 16); }
__device__ __forceinline__ float bf_hi(unsigned int u) { return __uint_as_float(u & 0xffff0000u); }

__device__ __forceinline__ unsigned int ld_acq(const unsigned int* p) {
    unsigned int v;
    asm volatile("ld.acquire.gpu.global.u32 %0, [%1];" : "=r"(v) : "l"(p) : "memory");
    return v;
}
__device__ __forceinline__ void st_rel(unsigned int* p, unsigned int v) {
    asm volatile("st.release.gpu.global.u32 [%0], %1;" :: "l"(p), "r"(v) : "memory");
}

// Fence-free 2-hop grid barrier (one writer + ONE poller per flag line).
__device__ __forceinline__ void grid_barrier(unsigned int& gen, int tid, int bid) {
    __syncthreads();
    ++gen;
    if (bid == 0) {
        if (tid == 0) st_rel(&g_flags[0], gen);
        if (tid > 0 && tid < NBLK) {
            const unsigned int* f = &g_flags[tid * 64];
            while ((int)(ld_acq(f) - gen) < 0) { }
        }
        __syncthreads();
        if (tid == 0) st_rel(&g_bar_gen, gen);
    } else {
        if (tid == 0) {
            st_rel(&g_flags[bid * 64], gen);
            while ((int)(ld_acq(&g_bar_gen) - gen) < 0) { }
        }
        __syncthreads();
    }
}

__device__ __forceinline__ float dot8(uint4 q, float4 va, float4 vb, float acc) {
    acc += bf_lo(q.x) * va.x + bf_hi(q.x) * va.y
         + bf_lo(q.y) * va.z + bf_hi(q.y) * va.w
         + bf_lo(q.z) * vb.x + bf_hi(q.z) * vb.y
         + bf_lo(q.w) * vb.z + bf_hi(q.w) * vb.w;
    return acc;
}

__device__ __forceinline__ float tf32r(float f) {
    asm("cvt.rna.tf32.f32 %0, %0;" : "+f"(f));
    return f;
}

// D += A(16x8,row) * B(8x8,col) tf32 tensor-core MMA
__device__ __forceinline__ void mma_tf32(float* c, const unsigned* a, const unsigned* b) {
    asm volatile(
        "mma.sync.aligned.m16n8k8.row.col.f32.tf32.tf32.f32 "
        "{%0,%1,%2,%3}, {%4,%5,%6,%7}, {%8,%9}, {%0,%1,%2,%3};\n"
        : "+f"(c[0]), "+f"(c[1]), "+f"(c[2]), "+f"(c[3])
        : "r"(a[0]), "r"(a[1]), "r"(a[2]), "r"(a[3]), "r"(b[0]), "r"(b[1]));
}

__global__ __launch_bounds__(NTHR, 1) void ot_kernel(
    const float* __restrict__ z0, const float* __restrict__ z1,
    const float* __restrict__ z2, float* __restrict__ out)
{
    // GEMM: sA[128][36] + sB[128][36] fp32 (36.9KB). Pass phases reuse s_mem.
    __shared__ __align__(16) float s_mem[2 * 128 * 36];
    __shared__ float s_part[28 * 9];
    __shared__ float s_u[28];
    __shared__ double s_dval[28];

    const int tid  = threadIdx.x;
    const int bid  = blockIdx.x;
    const int wid  = tid >> 5;
    const int lane = tid & 31;
    const int rb    = (int)(((long long)bid * NN) / NBLK);
    const int re    = (int)(((long long)(bid + 1) * NN) / NBLK);
    const int nrows = re - rb;                      // 27 or 28

    unsigned int gen = __ldcg(&g_bar_gen);          // monotonic across graph replays

    if (bid == 0 && tid == 0) g_loss = 0.0;

    const float* Z[3] = { z0, z1, z2 };
    const int XI[3] = { 0, 0, 1 };
    const int YI[3] = { 1, 2, 2 };

    // ---------- Phase 0 (once): row norms of z0,z1,z2 ----------
    for (int r = bid * NWARP + wid; r < 3 * NN; r += NBLK * NWARP) {
        const float* src = Z[r >> 12];
        int row = r & (NN - 1);
        float4 v4 = ((const float4*)(src + (size_t)row * DD))[lane];
        float s = v4.x * v4.x + v4.y * v4.y + v4.z * v4.z + v4.w * v4.w;
        #pragma unroll
        for (int o = 16; o; o >>= 1) s += __shfl_xor_sync(0xffffffffu, s, o);
        if (lane == 0) g_nsq[r] = s;
    }
    grid_barrier(gen, tid, bid);

    #pragma unroll 1
    for (int pr = 0; pr < 3; ++pr) {
        const float* x = Z[XI[pr]];
        const float* y = Z[YI[pr]];
        const float* xsq = g_nsq + XI[pr] * NN;
        const float* ysq = g_nsq + YI[pr] * NN;

        // ---------- Phase 2: K = exp(-C/REG) -> Kb via tf32 tensor cores ----------
        {
            float* sA = s_mem;                   // [128 m][36]  x tile (tf32-rounded)
            float* sB = s_mem + 128 * 36;        // [128 n][36]  y tile (tf32-rounded)
            const int mw = wid >> 2;             // 0..7  (16-row block)
            const int nw = wid & 3;              // 0..3  (32-col block)
            const int NT = (NN / 128) * (NN / 128);   // 1024 tiles

            #pragma unroll 1
            for (int t = bid; t < NT; t += NBLK) {
                const int r0 = (t >> 5) * 128;
                const int c0 = (t & 31) * 128;

                float cf[4][4];
                #pragma unroll
                for (int nf = 0; nf < 4; ++nf)
                    #pragma unroll
                    for (int q = 0; q < 4; ++q) cf[nf][q] = 0.f;

                #pragma unroll 1
                for (int kc = 0; kc < DD; kc += 32) {
                    __syncthreads();
                    #pragma unroll
                    for (int idx = tid; idx < 128 * 32; idx += NTHR) {
                        int rr = idx >> 5, cc = idx & 31;
                        sA[rr * 36 + cc] = tf32r(x[(size_t)(r0 + rr) * DD + kc + cc]);
                        sB[rr * 36 + cc] = tf32r(y[(size_t)(c0 + rr) * DD + kc + cc]);
                    }
                    __syncthreads();
                    #pragma unroll 1
                    for (int ks = 0; ks < 4; ++ks) {
                        const int kb = ks * 8;
                        const int ar = mw * 16 + (lane >> 2);
                        const int ac = kb + (lane & 3);
                        unsigned a[4];
                        a[0] = __float_as_uint(sA[ar * 36 + ac]);
                        a[1] = __float_as_uint(sA[(ar + 8) * 36 + ac]);
                        a[2] = __float_as_uint(sA[ar * 36 + ac + 4]);
                        a[3] = __float_as_uint(sA[(ar + 8) * 36 + ac + 4]);
                        #pragma unroll
                        for (int nf = 0; nf < 4; ++nf) {
                            const int bn = nw * 32 + nf * 8 + (lane >> 2);
                            const int bk = kb + (lane & 3);
                            unsigned b[2];
                            b[0] = __float_as_uint(sB[bn * 36 + bk]);
                            b[1] = __float_as_uint(sB[bn * 36 + bk + 4]);
                            mma_tf32(cf[nf], a, b);
                        }
                    }
                }

                // Epilogue: C = clip(xsq + ysq - 2D, 0); K = exp(-C/REG) -> bf16
                const int i0m = r0 + mw * 16 + (lane >> 2);   // rows i0m, i0m+8
                const float xs0 = __ldcg(&xsq[i0m]);
                const float xs1 = __ldcg(&xsq[i0m + 8]);
                #pragma unroll
                for (int nf = 0; nf < 4; ++nf) {
                    const int col = c0 + nw * 32 + nf * 8 + (lane & 3) * 2;
                    const float ys0 = __ldcg(&ysq[col]);
                    const float ys1 = __ldcg(&ysq[col + 1]);
                    float e00 = __expf(-fmaxf(xs0 + ys0 - 2.f * cf[nf][0], 0.f) * (1.0f / REGC));
                    float e01 = __expf(-fmaxf(xs0 + ys1 - 2.f * cf[nf][1], 0.f) * (1.0f / REGC));
                    float e10 = __expf(-fmaxf(xs1 + ys0 - 2.f * cf[nf][2], 0.f) * (1.0f / REGC));
                    float e11 = __expf(-fmaxf(xs1 + ys1 - 2.f * cf[nf][3], 0.f) * (1.0f / REGC));
                    __nv_bfloat162 p0 = __floats2bfloat162_rn(e00, e01);
                    __nv_bfloat162 p1 = __floats2bfloat162_rn(e10, e11);
                    *(unsigned int*)(g_Kb + (size_t)i0m * NN + col)       = *(unsigned int*)&p0;
                    *(unsigned int*)(g_Kb + (size_t)(i0m + 8) * NN + col) = *(unsigned int*)&p1;
                }
            }
            if (tid < nrows) s_u[tid] = 1.0f;        // u is CTA-local
        }
        grid_barrier(gen, tid, bid);
        if (tid == 0) __threadfence();               // CCTL.IVALL: drop stale K lines
        __syncthreads();

        // ---------- Phase 3: NITER Sinkhorn iterations, K stripe L1-resident ----------
        #pragma unroll 1
        for (int it = 0; it < NITER; ++it) {
            // (a) column partials over own rows: part[j] = sum_r K[rb+r, j] * u[r]
            {
                const int j0 = (wid << 7) + (lane << 2);      // warp: 128 cols
                float a0 = 0.f, a1 = 0.f, a2 = 0.f, a3 = 0.f;
                const int nl1 = (nrows < L1ROWS) ? nrows : L1ROWS;
                int r = 0;
                #pragma unroll 4
                for (; r < nl1; ++r) {
                    uint2 q = *(const uint2*)(g_Kb + (size_t)(rb + r) * NN + j0);
                    float ur = s_u[r];
                    a0 += bf_lo(q.x) * ur; a1 += bf_hi(q.x) * ur;
                    a2 += bf_lo(q.y) * ur; a3 += bf_hi(q.y) * ur;
                }
                #pragma unroll 1
                for (; r < nrows; ++r) {
                    uint2 q = __ldcg((const uint2*)(g_Kb + (size_t)(rb + r) * NN + j0));
                    float ur = s_u[r];
                    a0 += bf_lo(q.x) * ur; a1 += bf_hi(q.x) * ur;
                    a2 += bf_lo(q.y) * ur; a3 += bf_hi(q.y) * ur;
                }
                *(float4*)(g_part + (size_t)bid * NN + j0) = make_float4(a0, a1, a2, a3);
            }
            grid_barrier(gen, tid, bid);

            // (b) v-reduce: CTA owns cols [rb,re); all 148 CTAs work
            {
                const int ncols = nrows;
                float a = 0.f;
                if (lane < ncols) {
                    #pragma unroll 1
                    for (int c = wid; c < NBLK; c += NWARP)
                        a += __ldcg(&g_part[(size_t)c * NN + rb + lane]);
                }
                s_mem[wid * 36 + lane] = a;
                __syncthreads();
                if (wid == 0 && lane < ncols) {
                    float s = 0.f;
                    #pragma unroll
                    for (int w = 0; w < NWARP; ++w) s += s_mem[w * 36 + lane];
                    g_v[rb + lane] = MUNU / (s + EPSC);
                }
            }
            grid_barrier(gen, tid, bid);

            // (c) row pass: u[r] = MUNU / (dot(K[rb+r,:], v) + EPS) -> s_u (local)
            {
                const int gr = wid >> 3;                  // 4 groups x 7 rows
                const int jh = wid & 7;                   // 8 slices x 512 cols
                const int r0 = gr * 7;
                const int nr = nrows - r0;

                const float4* v4 = (const float4*)g_v + jh * 128;
                float4 va0 = __ldcg(v4 + 2 * lane);
                float4 vb0 = __ldcg(v4 + 2 * lane + 1);
                float4 va1 = __ldcg(v4 + 2 * (lane + 32));
                float4 vb1 = __ldcg(v4 + 2 * (lane + 32) + 1);

                float acc[7];
                #pragma unroll
                for (int r = 0; r < 7; ++r) {
                    int ri = r0 + r;
                    ri = (ri < nrows) ? ri : (nrows - 1);     // clamp; discarded below
                    const uint4* kr = (const uint4*)(g_Kb + (size_t)(rb + ri) * NN) + jh * 64;
                    uint4 q0, q1;
                    if (ri < L1ROWS) { q0 = kr[lane]; q1 = kr[lane + 32]; }
                    else { q0 = __ldcg(kr + lane); q1 = __ldcg(kr + lane + 32); }
                    float a = dot8(q0, va0, vb0, 0.f);
                    acc[r] = dot8(q1, va1, vb1, a);
                }
                #pragma unroll
                for (int o = 16; o; o >>= 1) {
                    #pragma unroll
                    for (int r = 0; r < 7; ++r)
                        acc[r] += __shfl_xor_sync(0xffffffffu, acc[r], o);
                }
                if (lane == 0) {
                    #pragma unroll
                    for (int r = 0; r < 7; ++r)
                        if (r < nr) s_part[(r0 + r) * 9 + jh] = acc[r];
                }
                __syncthreads();
                if (tid < nrows) {
                    const float* pp = s_part + tid * 9;
                    float s = pp[0] + pp[1] + pp[2] + pp[3] + pp[4] + pp[5] + pp[6] + pp[7];
                    s_u[tid] = MUNU / (s + EPSC);
                }
                __syncthreads();
            }
            // no barrier: next col-partial needs only this CTA's own u
        }

        // ---------- Phase 4: loss += sum u_i K_ij v_j * (-REG * ln K_ij) ----------
        {
            const int gr = wid >> 3;
            const int jh = wid & 7;
            const int r0 = gr * 7;
            const int nr = nrows - r0;

            const float4* v4 = (const float4*)g_v + jh * 128;
            float4 va0 = __ldcg(v4 + 2 * lane);
            float4 vb0 = __ldcg(v4 + 2 * lane + 1);
            float4 va1 = __ldcg(v4 + 2 * (lane + 32));
            float4 vb1 = __ldcg(v4 + 2 * (lane + 32) + 1);

            float acc[7];
            #pragma unroll 1
            for (int r = 0; r < 7; ++r) {
                int ri = r0 + r;
                ri = (ri < nrows) ? ri : (nrows - 1);
                const uint4* kr = (const uint4*)(g_Kb + (size_t)(rb + ri) * NN) + jh * 64;
                uint4 q0 = kr[lane];
                uint4 q1 = kr[lane + 32];
                float a = 0.f, f;
                f = bf_lo(q0.x); a += f * va0.x * __logf(f);
                f = bf_hi(q0.x); a += f * va0.y * __logf(f);
                f = bf_lo(q0.y); a += f * va0.z * __logf(f);
                f = bf_hi(q0.y); a += f * va0.w * __logf(f);
                f = bf_lo(q0.z); a += f * vb0.x * __logf(f);
                f = bf_hi(q0.z); a += f * vb0.y * __logf(f);
                f = bf_lo(q0.w); a += f * vb0.z * __logf(f);
                f = bf_hi(q0.w); a += f * vb0.w * __logf(f);
                f = bf_lo(q1.x); a += f * va1.x * __logf(f);
                f = bf_hi(q1.x); a += f * va1.y * __logf(f);
                f = bf_lo(q1.y); a += f * va1.z * __logf(f);
                f = bf_hi(q1.y); a += f * va1.w * __logf(f);
                f = bf_lo(q1.z); a += f * vb1.x * __logf(f);
                f = bf_hi(q1.z); a += f * vb1.y * __logf(f);
                f = bf_lo(q1.w); a += f * vb1.z * __logf(f);
                f = bf_hi(q1.w); a += f * vb1.w * __logf(f);
                acc[r] = a;
            }
            #pragma unroll
            for (int o = 16; o; o >>= 1) {
                #pragma unroll
                for (int r = 0; r < 7; ++r)
                    acc[r] += __shfl_xor_sync(0xffffffffu, acc[r], o);
            }
            if (lane == 0) {
                #pragma unroll
                for (int r = 0; r < 7; ++r)
                    if (r < nr) s_part[(r0 + r) * 9 + jh] = acc[r];
            }
            __syncthreads();
            if (tid < nrows) {
                const float* pp = s_part + tid * 9;
                float tot = pp[0] + pp[1] + pp[2] + pp[3] + pp[4] + pp[5] + pp[6] + pp[7];
                s_dval[tid] = (double)s_u[tid] * (double)tot;
            }
            __syncthreads();
            if (tid == 0) {
                double c = 0.0;
                for (int i = 0; i < nrows; ++i) c += s_dval[i];
                atomicAdd(&g_loss, (double)(-REGC) * c);
            }
        }
        grid_barrier(gen, tid, bid);   // protect Kb/g_v before next pair overwrites
    }

    if (bid == 0 && tid == 0) {
        double l;
        asm volatile("ld.global.cg.f64 %0, [%1];" : "=d"(l) : "l"(&g_loss));
        out[0] = (float)(l / 3.0);
    }
}

extern "C" void kernel_launch(void* const* d_in, const int* in_sizes, int n_in,
                              void* d_out, int out_size) {
    (void)in_sizes; (void)n_in; (void)out_size;
    const float* z0 = (const float*)d_in[0];
    const float* z1 = (const float*)d_in[1];
    const float* z2 = (const float*)d_in[2];
    ot_kernel<<<NBLK, NTHR>>>(z0, z1, z2, (float*)d_out);
}